// round 11
// baseline (speedup 1.0000x reference)
#include <cuda_runtime.h>
#include <cstdint>
#include <math.h>

// AttentionAggregator via TMA bulk-copy gathers.
// Theory: all prior variants (reg-resident / cp.async / streaming / chain-
// free) plateau at ~10.3us kernel = ~4TB/s effective gather throughput with
// nothing saturated -> the shared element is the LSU/L1tex miss path (MSHR x
// latency ~ 16-30 B/cyc/SM). This version routes row gathers through the TMA
// engine (cp.async.bulk.shared::cta.global + mbarrier complete_tx), which
// bypasses L1 miss tracking and sustains the LTS cap.
// features: [100000, 256] f32; nodes: [4096] i32; unique_ids: [16384] i32;
// neigh_idx: [4096, 10] i32. out: [4096, 256] f32.

#define N_NODES 4096
#define FDIM    256
#define NSAMP   10
#define WARPS   8
#define ROW_BYTES 1024
#define WARP_SMEM (11 * ROW_BYTES)        // q + 10 embed rows = 11264 B
#define DATA_SMEM (WARPS * WARP_SMEM)     // 90112 B
#define SMEM_TOTAL (DATA_SMEM + WARPS * 8)

__device__ __forceinline__ void bulk_cp_1k(unsigned int dst, const void* src,
                                           unsigned int mbar) {
    asm volatile(
        "cp.async.bulk.shared::cta.global.mbarrier::complete_tx::bytes "
        "[%0], [%1], %2, [%3];"
        :: "r"(dst), "l"(src), "r"((unsigned)ROW_BYTES), "r"(mbar) : "memory");
}

__device__ __forceinline__ void stcs128(float* p, float4 v) {
    asm volatile("st.global.cs.v4.f32 [%0], {%1,%2,%3,%4};"
                 :: "l"(p), "f"(v.x), "f"(v.y), "f"(v.z), "f"(v.w));
}

__global__ __launch_bounds__(WARPS * 32)
void attn_agg_kernel(const float* __restrict__ feat,
                     const int*   __restrict__ nodes,
                     const int*   __restrict__ uids,
                     const int*   __restrict__ nidx,
                     float*       __restrict__ out)
{
    extern __shared__ char smem[];
    const int warp = threadIdx.x >> 5;
    const int lane = threadIdx.x & 31;
    const int row  = blockIdx.x * WARPS + warp;

    char* wdata = smem + warp * WARP_SMEM;
    const unsigned int sdata =
        (unsigned int)__cvta_generic_to_shared(wdata);
    const unsigned int smbar =
        (unsigned int)__cvta_generic_to_shared(smem + DATA_SMEM + warp * 8);

    // --- indices (warp-uniform). nidx row = 40B, 8B-aligned -> 5x int2 ---
    int cols[NSAMP];
    {
        const int2* np = (const int2*)(nidx + (size_t)row * NSAMP);
        #pragma unroll
        for (int i = 0; i < 5; i++) {
            int2 v = np[i];
            cols[2*i+0] = v.x;
            cols[2*i+1] = v.y;
        }
    }
    int uid[NSAMP];
    #pragma unroll
    for (int s = 0; s < NSAMP; s++)
        uid[s] = uids[cols[s]];
    const int node = nodes[row];

    // --- per-warp mbarrier init, then elected lane fires 11 TMA bulk copies ---
    if (lane == 0) {
        asm volatile("mbarrier.init.shared.b64 [%0], %1;"
                     :: "r"(smbar), "r"(1) : "memory");
    }
    __syncwarp();

    if (lane == 0) {
        asm volatile("mbarrier.arrive.expect_tx.shared.b64 _, [%0], %1;"
                     :: "r"(smbar), "r"((unsigned)WARP_SMEM) : "memory");
        bulk_cp_1k(sdata, feat + (size_t)node * FDIM, smbar);
        #pragma unroll
        for (int s = 0; s < NSAMP; s++)
            bulk_cp_1k(sdata + (unsigned)(1 + s) * ROW_BYTES,
                       feat + (size_t)uid[s] * FDIM, smbar);
    }

    // --- dedup mask while copies fly (dense mask counts repeated cols once) ---
    unsigned dup = 0;
    #pragma unroll
    for (int s = 1; s < NSAMP; s++) {
        bool d = false;
        #pragma unroll
        for (int t = 0; t < NSAMP; t++)
            if (t < s) d |= (cols[t] == cols[s]);
        if (d) dup |= (1u << s);
    }

    // --- wait for this warp's 11KB (acquire orders LDS after TMA writes) ---
    {
        unsigned int done;
        asm volatile(
            "{\n\t.reg .pred p;\n\t"
            "mbarrier.try_wait.parity.acquire.cta.shared::cta.b64 p, [%1], %2;\n\t"
            "selp.b32 %0, 1, 0, p;\n\t}"
            : "=r"(done) : "r"(smbar), "r"(0u) : "memory");
        if (!done) {
            asm volatile(
                "{\n\t.reg .pred P1;\n\t"
                "WL_%=:\n\t"
                "mbarrier.try_wait.parity.acquire.cta.shared::cta.b64 P1, [%0], %1, 0x989680;\n\t"
                "@P1 bra.uni WD_%=;\n\t"
                "bra.uni WL_%=;\n\t"
                "WD_%=:\n\t}"
                :: "r"(smbar), "r"(0u) : "memory");
        }
    }

    // --- compute from SMEM: dots + butterfly reduce ---
    const float4* qf = (const float4*)wdata;
    const float4 q0 = qf[lane];
    const float4 q1 = qf[lane + 32];

    float dots[NSAMP];
    #pragma unroll
    for (int s = 0; s < NSAMP; s++) {
        const float4* ep = (const float4*)(wdata + (1 + s) * ROW_BYTES);
        const float4 b0 = ep[lane];
        const float4 b1 = ep[lane + 32];
        float a = b0.x*q0.x + b0.y*q0.y + b0.z*q0.z + b0.w*q0.w
                + b1.x*q1.x + b1.y*q1.y + b1.z*q1.z + b1.w*q1.w;
        #pragma unroll
        for (int o = 16; o; o >>= 1)
            a += __shfl_xor_sync(0xffffffffu, a, o);
        dots[s] = a;
    }

    // --- softmax over distinct columns (redundant per lane) ---
    float m = -INFINITY;
    #pragma unroll
    for (int s = 0; s < NSAMP; s++)
        if (!((dup >> s) & 1u)) m = fmaxf(m, dots[s]);
    float sum = 0.f;
    #pragma unroll
    for (int s = 0; s < NSAMP; s++) {
        float e = ((dup >> s) & 1u) ? 0.f : __expf(dots[s] - m);
        dots[s] = e;
        sum += e;
    }
    const float inv = 1.f / sum;

    // --- aggregation from SMEM + streaming store ---
    float4 o0 = make_float4(0.f, 0.f, 0.f, 0.f);
    float4 o1 = make_float4(0.f, 0.f, 0.f, 0.f);
    #pragma unroll
    for (int s = 0; s < NSAMP; s++) {
        const float ws = dots[s] * inv;
        const float4* ep = (const float4*)(wdata + (1 + s) * ROW_BYTES);
        const float4 b0 = ep[lane];
        const float4 b1 = ep[lane + 32];
        o0.x += ws*b0.x; o0.y += ws*b0.y;
        o0.z += ws*b0.z; o0.w += ws*b0.w;
        o1.x += ws*b1.x; o1.y += ws*b1.y;
        o1.z += ws*b1.z; o1.w += ws*b1.w;
    }
    float* op = out + (size_t)row * FDIM;
    stcs128(op + lane * 4, o0);
    stcs128(op + (lane + 32) * 4, o1);
}

extern "C" void kernel_launch(void* const* d_in, const int* in_sizes, int n_in,
                              void* d_out, int out_size)
{
    const float* feat  = (const float*)d_in[0];
    const int*   nodes = (const int*)  d_in[1];
    const int*   uids  = (const int*)  d_in[2];
    const int*   nidx  = (const int*)  d_in[3];
    float*       out   = (float*)d_out;
    (void)in_sizes; (void)n_in; (void)out_size;

    cudaFuncSetAttribute(attn_agg_kernel,
                         cudaFuncAttributeMaxDynamicSharedMemorySize,
                         SMEM_TOTAL);
    attn_agg_kernel<<<N_NODES / WARPS, WARPS * 32, SMEM_TOTAL>>>(
        feat, nodes, uids, nidx, out);
}